// round 3
// baseline (speedup 1.0000x reference)
#include <cuda_runtime.h>
#include <math.h>

// ---------------- problem constants ----------------
#define B_SZ    2
#define SEQ_L   2048
#define D_MODEL 1024
#define D_STATE 16
#define D_CONV  4
#define D_INNER 2048
#define DT_RANK 64
#define M_TOTAL (B_SZ * SEQ_L)   // 4096 tokens

// ---------------- scratch (device globals; no allocation allowed) ----------------
__device__ float g_xz[(size_t)M_TOTAL * 2 * D_INNER];   // in_proj output: [4096, 4096] (x_in | z)
__device__ float g_xconv[(size_t)M_TOTAL * D_INNER];    // conv+silu output
__device__ float g_xbc[(size_t)M_TOTAL * 96];           // [xdt(64) | B(16) | C(16)]
__device__ float g_dt[(size_t)M_TOTAL * D_INNER];       // softplus dt
__device__ float g_y[(size_t)M_TOTAL * D_INNER];        // scan output (gated)
__device__ float g_wcat[96 * D_INNER];                  // concat [x_proj_w; B_proj_w; C_proj_w]

// ---------------- generic fp32 GEMM: C[m,n] = act(sum_k A[m,k]*W[n,k] (+bias)) ----------------
// A: row-major [M, lda>=K], W: row-major [N, ldw>=K] (i.e. computes A @ W^T)
// ACT: 0 = none, 1 = softplus(v + bias[n])
template<int BM, int BN, int BK, int TM, int TN, int ACT>
__global__ void sgemm_kernel(const float* __restrict__ A, int lda,
                             const float* __restrict__ W, int ldw,
                             const float* __restrict__ bias,
                             float* __restrict__ C, int ldc,
                             int M, int N, int K)
{
    constexpr int THREADS = (BM / TM) * (BN / TN);
    __shared__ float As[BK][BM];
    __shared__ float Ws[BK][BN];

    const int tid = threadIdx.x;
    const int tx  = tid % (BN / TN);   // n direction
    const int ty  = tid / (BN / TN);   // m direction
    const int m0  = blockIdx.y * BM;
    const int n0  = blockIdx.x * BN;

    float acc[TM][TN];
#pragma unroll
    for (int i = 0; i < TM; i++)
#pragma unroll
        for (int j = 0; j < TN; j++) acc[i][j] = 0.f;

    for (int k0 = 0; k0 < K; k0 += BK) {
        // load A tile (BM x BK) as float4 along K, store transposed
        for (int e = tid * 4; e < BM * BK; e += THREADS * 4) {
            int row = e / BK, kk = e % BK;
            float4 v = *(const float4*)(A + (size_t)(m0 + row) * lda + k0 + kk);
            As[kk + 0][row] = v.x; As[kk + 1][row] = v.y;
            As[kk + 2][row] = v.z; As[kk + 3][row] = v.w;
        }
        // load W tile (BN x BK)
        for (int e = tid * 4; e < BN * BK; e += THREADS * 4) {
            int row = e / BK, kk = e % BK;
            float4 v = *(const float4*)(W + (size_t)(n0 + row) * ldw + k0 + kk);
            Ws[kk + 0][row] = v.x; Ws[kk + 1][row] = v.y;
            Ws[kk + 2][row] = v.z; Ws[kk + 3][row] = v.w;
        }
        __syncthreads();

#pragma unroll
        for (int kk = 0; kk < BK; kk++) {
            float a[TM], w[TN];
#pragma unroll
            for (int i = 0; i < TM; i++) a[i] = As[kk][ty * TM + i];
#pragma unroll
            for (int j = 0; j < TN; j++) w[j] = Ws[kk][tx * TN + j];
#pragma unroll
            for (int i = 0; i < TM; i++)
#pragma unroll
                for (int j = 0; j < TN; j++)
                    acc[i][j] = fmaf(a[i], w[j], acc[i][j]);
        }
        __syncthreads();
    }

#pragma unroll
    for (int i = 0; i < TM; i++) {
        int m = m0 + ty * TM + i;
#pragma unroll
        for (int j = 0; j < TN; j++) {
            int n = n0 + tx * TN + j;
            float v = acc[i][j];
            if (ACT == 1) {
                v += bias[n];
                v = (v > 20.f) ? v : log1pf(expf(v));   // softplus
            }
            C[(size_t)m * ldc + n] = v;
        }
    }
}

// ---------------- causal depthwise conv (width 4) + SiLU ----------------
__global__ void conv_silu_kernel(const float* __restrict__ conv_w,
                                 const float* __restrict__ conv_b)
{
    int idx = blockIdx.x * blockDim.x + threadIdx.x;
    if (idx >= M_TOTAL * D_INNER) return;
    int d  = idx % D_INNER;
    int ml = idx / D_INNER;      // b*L + l
    int l  = ml % SEQ_L;

    float acc = conv_b[d];
    const float* w = conv_w + d * D_CONV;
#pragma unroll
    for (int j = 0; j < D_CONV; j++) {
        int li = l - (D_CONV - 1) + j;
        if (li >= 0)
            acc = fmaf(w[j], g_xz[(size_t)(ml - (D_CONV - 1) + j) * (2 * D_INNER) + d], acc);
    }
    g_xconv[idx] = acc / (1.f + expf(-acc));   // silu
}

// ---------------- selective scan (+ D skip + z gating) ----------------
// 16 lanes = 16 states per channel; 2 channels per warp; 2048 warps total.
__global__ void scan_kernel(const float* __restrict__ A_log,
                            const float* __restrict__ Dp)
{
    int gwarp = (blockIdx.x * blockDim.x + threadIdx.x) >> 5;
    int lane  = threadIdx.x & 31;
    int half  = lane >> 4;       // which channel within the warp
    int s     = lane & 15;       // state index
    int ch    = gwarp * 2 + half;        // 0..4095
    int b     = ch / D_INNER;
    int d     = ch % D_INNER;

    const float Acoef = -expf(A_log[d * D_STATE + s]);
    const float Dv    = Dp[d];

    const float* xrow  = g_xconv + (size_t)b * SEQ_L * D_INNER + d;
    const float* dtrow = g_dt    + (size_t)b * SEQ_L * D_INNER + d;
    const float* bcrow = g_xbc   + (size_t)b * SEQ_L * 96;
    const float* zrow  = g_xz    + (size_t)b * SEQ_L * (2 * D_INNER) + D_INNER + d;
    float*       yrow  = g_y     + (size_t)b * SEQ_L * D_INNER + d;

    float h = 0.f;
    for (int t = 0; t < SEQ_L; t++) {
        float xv  = xrow [(size_t)t * D_INNER];
        float dtv = dtrow[(size_t)t * D_INNER];
        float Bv  = bcrow[t * 96 + DT_RANK + s];
        float Cv  = bcrow[t * 96 + DT_RANK + D_STATE + s];

        // h = h + dt*(A*h) + dt*(B*x)
        h = fmaf(dtv, fmaf(Acoef, h, Bv * xv), h);

        float p = h * Cv;
        p += __shfl_xor_sync(0xffffffffu, p, 8);
        p += __shfl_xor_sync(0xffffffffu, p, 4);
        p += __shfl_xor_sync(0xffffffffu, p, 2);
        p += __shfl_xor_sync(0xffffffffu, p, 1);

        if (s == 0) {
            float zv = zrow[(size_t)t * (2 * D_INNER)];
            float y  = fmaf(Dv, xv, p);
            y *= zv / (1.f + expf(-zv));       // * silu(z)
            yrow[(size_t)t * D_INNER] = y;
        }
    }
}

// ---------------- launch ----------------
extern "C" void kernel_launch(void* const* d_in, const int* in_sizes, int n_in,
                              void* d_out, int out_size)
{
    const float* x          = (const float*)d_in[0];
    const float* in_proj_w  = (const float*)d_in[1];
    const float* conv_w     = (const float*)d_in[2];
    const float* conv_b     = (const float*)d_in[3];
    const float* A_log      = (const float*)d_in[4];
    const float* Dp         = (const float*)d_in[5];
    const float* dt_proj_w  = (const float*)d_in[6];
    const float* dt_proj_b  = (const float*)d_in[7];
    const float* x_proj_w   = (const float*)d_in[8];
    const float* B_proj_w   = (const float*)d_in[9];
    const float* C_proj_w   = (const float*)d_in[10];
    const float* out_proj_w = (const float*)d_in[11];
    float* out = (float*)d_out;

    // resolve scratch addresses
    float *xz, *xconv, *xbc, *dt, *y, *wcat;
    cudaGetSymbolAddress((void**)&xz,    g_xz);
    cudaGetSymbolAddress((void**)&xconv, g_xconv);
    cudaGetSymbolAddress((void**)&xbc,   g_xbc);
    cudaGetSymbolAddress((void**)&dt,    g_dt);
    cudaGetSymbolAddress((void**)&y,     g_y);
    cudaGetSymbolAddress((void**)&wcat,  g_wcat);

    // pack [x_proj_w; B_proj_w; C_proj_w] -> g_wcat (96 x 2048)
    cudaMemcpyToSymbolAsync(g_wcat, x_proj_w, (size_t)DT_RANK * D_INNER * sizeof(float),
                            0, cudaMemcpyDeviceToDevice, 0);
    cudaMemcpyToSymbolAsync(g_wcat, B_proj_w, (size_t)D_STATE * D_INNER * sizeof(float),
                            (size_t)DT_RANK * D_INNER * sizeof(float), cudaMemcpyDeviceToDevice, 0);
    cudaMemcpyToSymbolAsync(g_wcat, C_proj_w, (size_t)D_STATE * D_INNER * sizeof(float),
                            (size_t)(DT_RANK + D_STATE) * D_INNER * sizeof(float), cudaMemcpyDeviceToDevice, 0);

    // 1) in_proj: xz = x @ in_proj_w^T   (4096 x 4096, K=1024)
    {
        dim3 grid(2 * D_INNER / 128, M_TOTAL / 128);
        sgemm_kernel<128, 128, 16, 8, 8, 0><<<grid, 256>>>(
            x, D_MODEL, in_proj_w, D_MODEL, nullptr, xz, 2 * D_INNER,
            M_TOTAL, 2 * D_INNER, D_MODEL);
    }

    // 2) causal depthwise conv + silu -> g_xconv
    {
        int n = M_TOTAL * D_INNER;
        conv_silu_kernel<<<(n + 255) / 256, 256>>>(conv_w, conv_b);
    }

    // 3) fused x/B/C projection: xbc = xconv @ wcat^T   (4096 x 96, K=2048)
    {
        dim3 grid(1, M_TOTAL / 32);
        sgemm_kernel<32, 96, 16, 2, 3, 0><<<grid, 512>>>(
            xconv, D_INNER, wcat, D_INNER, nullptr, xbc, 96,
            M_TOTAL, 96, D_INNER);
    }

    // 4) dt = softplus(xbc[:, :64] @ dt_proj_w^T + dt_proj_b)   (4096 x 2048, K=64)
    {
        dim3 grid(D_INNER / 128, M_TOTAL / 128);
        sgemm_kernel<128, 128, 16, 8, 8, 1><<<grid, 256>>>(
            xbc, 96, dt_proj_w, DT_RANK, dt_proj_b, dt, D_INNER,
            M_TOTAL, D_INNER, DT_RANK);
    }

    // 5) selective scan + D skip + silu(z) gating -> g_y
    {
        // 4096 channels * 16 states = 65536 lanes
        scan_kernel<<<256, 256>>>(A_log, Dp);
    }

    // 6) out = y @ out_proj_w^T   (4096 x 1024, K=2048)
    {
        dim3 grid(D_MODEL / 128, M_TOTAL / 128);
        sgemm_kernel<128, 128, 16, 8, 8, 0><<<grid, 256>>>(
            y, D_INNER, out_proj_w, D_INNER, nullptr, out, D_MODEL,
            M_TOTAL, D_MODEL, D_INNER);
    }
}

// round 5
// speedup vs baseline: 1.2739x; 1.2739x over previous
#include <cuda_runtime.h>
#include <math.h>
#include <stdint.h>

// ---------------- problem constants ----------------
#define B_SZ    2
#define SEQ_L   2048
#define D_MODEL 1024
#define D_STATE 16
#define D_CONV  4
#define D_INNER 2048
#define DT_RANK 64
#define M_TOTAL (B_SZ * SEQ_L)   // 4096 tokens
#define XBC_LD  128              // padded row stride for xbc / wcat

// ---------------- scratch (device globals; no allocation allowed) ----------------
__device__ float g_xz[(size_t)M_TOTAL * 2 * D_INNER];   // in_proj output: [4096, 4096] (x_in | z)
__device__ float g_xconv[(size_t)M_TOTAL * D_INNER];    // conv+silu output
__device__ float g_xbc[(size_t)M_TOTAL * XBC_LD];       // [xdt(64) | B(16) | C(16) | pad(32)]
__device__ float g_dt[(size_t)M_TOTAL * D_INNER];       // softplus dt
__device__ float g_y[(size_t)M_TOTAL * D_INNER];        // scan output (gated)
__device__ float g_wcat[XBC_LD * D_INNER];              // [x_proj_w; B_proj_w; C_proj_w; zeros]

// ---------------- tf32 helpers ----------------
__device__ __forceinline__ uint32_t f2tf32(float f) {
    uint32_t r;
    asm("cvt.rna.tf32.f32 %0, %1;" : "=r"(r) : "f"(f));
    return r;
}

__device__ __forceinline__ void mma_tf32(float* c, const uint32_t* a, const uint32_t* b) {
    asm volatile(
        "mma.sync.aligned.m16n8k8.row.col.f32.tf32.tf32.f32 "
        "{%0,%1,%2,%3},{%4,%5,%6,%7},{%8,%9},{%0,%1,%2,%3};"
        : "+f"(c[0]), "+f"(c[1]), "+f"(c[2]), "+f"(c[3])
        : "r"(a[0]), "r"(a[1]), "r"(a[2]), "r"(a[3]), "r"(b[0]), "r"(b[1]));
}

// ================= tf32 mma.sync GEMM =================
// C[m,n] = act( sum_k A[m,k] * W[n,k] (+ bias[n]) )
// BM = BN = 128, BK = 16. 256 threads = 8 warps (2 along m, 4 along n).
// Warp tile 64x32 -> 4 m16-tiles x 4 n8-tiles = 16 mma per k8 step.
// ACT: 0 = none, 1 = softplus(v + bias[n])
#define PITCH 136   // smem row pitch in floats (k-major); conflict-free for STS + frag LDS
template<int ACT>
__global__ __launch_bounds__(256)
void tc_gemm(const float* __restrict__ A, int lda,
             const float* __restrict__ W, int ldw,
             const float* __restrict__ bias,
             float* __restrict__ C, int ldc, int K)
{
    __shared__ uint32_t As[2][16 * PITCH];
    __shared__ uint32_t Bs[2][16 * PITCH];

    const int tid  = threadIdx.x;
    const int wid  = tid >> 5;
    const int lane = tid & 31;
    const int g    = lane >> 2;       // group id 0..7
    const int tg   = lane & 3;        // thread-in-group 0..3
    const int wm   = (wid & 1) * 64;  // warp m offset
    const int wn   = (wid >> 1) * 32; // warp n offset
    const int m0   = blockIdx.y * 128;
    const int n0   = blockIdx.x * 128;

    // loader mapping: 128 rows x 16 k; each thread owns 1 row-half (8 floats)
    const int lr = tid & 127;         // row within tile
    const int lj = tid >> 7;          // 0/1: which 8-float half of the k-chunk
    const float* aptr = A + (size_t)(m0 + lr) * lda + lj * 8;
    const float* wptr = W + (size_t)(n0 + lr) * ldw + lj * 8;

    float acc[4][4][4];
#pragma unroll
    for (int i = 0; i < 4; i++)
#pragma unroll
        for (int j = 0; j < 4; j++)
#pragma unroll
            for (int q = 0; q < 4; q++) acc[i][j][q] = 0.f;

    const int KC = K / 16;
    float4 va0, va1, vb0, vb1;

    // preload chunk 0
    va0 = *(const float4*)(aptr);     va1 = *(const float4*)(aptr + 4);
    vb0 = *(const float4*)(wptr);     vb1 = *(const float4*)(wptr + 4);
    {
        uint32_t* sa = As[0] + lj * 8 * PITCH + lr;
        uint32_t* sb = Bs[0] + lj * 8 * PITCH + lr;
        sa[0*PITCH] = f2tf32(va0.x); sa[1*PITCH] = f2tf32(va0.y);
        sa[2*PITCH] = f2tf32(va0.z); sa[3*PITCH] = f2tf32(va0.w);
        sa[4*PITCH] = f2tf32(va1.x); sa[5*PITCH] = f2tf32(va1.y);
        sa[6*PITCH] = f2tf32(va1.z); sa[7*PITCH] = f2tf32(va1.w);
        sb[0*PITCH] = f2tf32(vb0.x); sb[1*PITCH] = f2tf32(vb0.y);
        sb[2*PITCH] = f2tf32(vb0.z); sb[3*PITCH] = f2tf32(vb0.w);
        sb[4*PITCH] = f2tf32(vb1.x); sb[5*PITCH] = f2tf32(vb1.y);
        sb[6*PITCH] = f2tf32(vb1.z); sb[7*PITCH] = f2tf32(vb1.w);
    }
    __syncthreads();

    for (int c = 0; c < KC; c++) {
        const int buf = c & 1;
        if (c + 1 < KC) {             // prefetch next chunk into regs
            const int k0 = (c + 1) * 16;
            va0 = *(const float4*)(aptr + k0);  va1 = *(const float4*)(aptr + k0 + 4);
            vb0 = *(const float4*)(wptr + k0);  vb1 = *(const float4*)(wptr + k0 + 4);
        }

        const uint32_t* sA = As[buf];
        const uint32_t* sB = Bs[buf];
#pragma unroll
        for (int ks = 0; ks < 2; ks++) {
            const int kb = ks * 8;
            uint32_t af[4][4], bf[4][2];
#pragma unroll
            for (int mt = 0; mt < 4; mt++) {
                const int m = wm + mt * 16;
                af[mt][0] = sA[(kb + tg)     * PITCH + m + g];
                af[mt][1] = sA[(kb + tg)     * PITCH + m + g + 8];
                af[mt][2] = sA[(kb + tg + 4) * PITCH + m + g];
                af[mt][3] = sA[(kb + tg + 4) * PITCH + m + g + 8];
            }
#pragma unroll
            for (int nt = 0; nt < 4; nt++) {
                const int n = wn + nt * 8;
                bf[nt][0] = sB[(kb + tg)     * PITCH + n + g];
                bf[nt][1] = sB[(kb + tg + 4) * PITCH + n + g];
            }
#pragma unroll
            for (int mt = 0; mt < 4; mt++)
#pragma unroll
                for (int nt = 0; nt < 4; nt++)
                    mma_tf32(acc[mt][nt], af[mt], bf[nt]);
        }
        __syncthreads();

        if (c + 1 < KC) {             // stage prefetched regs into other buffer
            uint32_t* sa = As[buf ^ 1] + lj * 8 * PITCH + lr;
            uint32_t* sb = Bs[buf ^ 1] + lj * 8 * PITCH + lr;
            sa[0*PITCH] = f2tf32(va0.x); sa[1*PITCH] = f2tf32(va0.y);
            sa[2*PITCH] = f2tf32(va0.z); sa[3*PITCH] = f2tf32(va0.w);
            sa[4*PITCH] = f2tf32(va1.x); sa[5*PITCH] = f2tf32(va1.y);
            sa[6*PITCH] = f2tf32(va1.z); sa[7*PITCH] = f2tf32(va1.w);
            sb[0*PITCH] = f2tf32(vb0.x); sb[1*PITCH] = f2tf32(vb0.y);
            sb[2*PITCH] = f2tf32(vb0.z); sb[3*PITCH] = f2tf32(vb0.w);
            sb[4*PITCH] = f2tf32(vb1.x); sb[5*PITCH] = f2tf32(vb1.y);
            sb[6*PITCH] = f2tf32(vb1.z); sb[7*PITCH] = f2tf32(vb1.w);
            __syncthreads();
        }
    }

    // ---- epilogue: registers -> gmem (float2 per fragment row) ----
#pragma unroll
    for (int mt = 0; mt < 4; mt++) {
#pragma unroll
        for (int nt = 0; nt < 4; nt++) {
            const int row = m0 + wm + mt * 16 + g;
            const int col = n0 + wn + nt * 8 + 2 * tg;
            float v0 = acc[mt][nt][0], v1 = acc[mt][nt][1];
            float v2 = acc[mt][nt][2], v3 = acc[mt][nt][3];
            if (ACT == 1) {
                float b0 = bias[col], b1 = bias[col + 1];
                v0 += b0; v1 += b1; v2 += b0; v3 += b1;
                v0 = (v0 > 20.f) ? v0 : log1pf(expf(v0));
                v1 = (v1 > 20.f) ? v1 : log1pf(expf(v1));
                v2 = (v2 > 20.f) ? v2 : log1pf(expf(v2));
                v3 = (v3 > 20.f) ? v3 : log1pf(expf(v3));
            }
            *(float2*)(C + (size_t)row * ldc + col)       = make_float2(v0, v1);
            *(float2*)(C + (size_t)(row + 8) * ldc + col) = make_float2(v2, v3);
        }
    }
}

// ---------------- causal depthwise conv (width 4) + SiLU ----------------
__global__ void conv_silu_kernel(const float* __restrict__ conv_w,
                                 const float* __restrict__ conv_b)
{
    int idx = blockIdx.x * blockDim.x + threadIdx.x;
    if (idx >= M_TOTAL * D_INNER) return;
    int d  = idx % D_INNER;
    int ml = idx / D_INNER;      // b*L + l
    int l  = ml % SEQ_L;

    float acc = conv_b[d];
    const float* w = conv_w + d * D_CONV;
#pragma unroll
    for (int j = 0; j < D_CONV; j++) {
        int li = l - (D_CONV - 1) + j;
        if (li >= 0)
            acc = fmaf(w[j], g_xz[(size_t)(ml - (D_CONV - 1) + j) * (2 * D_INNER) + d], acc);
    }
    g_xconv[idx] = acc / (1.f + expf(-acc));   // silu
}

// ---------------- selective scan (+ D skip + z gating) ----------------
// 16 lanes = 16 states per channel; 2 channels per warp; 2048 warps total.
__global__ void scan_kernel(const float* __restrict__ A_log,
                            const float* __restrict__ Dp)
{
    int gwarp = (blockIdx.x * blockDim.x + threadIdx.x) >> 5;
    int lane  = threadIdx.x & 31;
    int half  = lane >> 4;       // which channel within the warp
    int s     = lane & 15;       // state index
    int ch    = gwarp * 2 + half;        // 0..4095
    int b     = ch / D_INNER;
    int d     = ch % D_INNER;

    const float Acoef = -expf(A_log[d * D_STATE + s]);
    const float Dv    = Dp[d];

    const float* xrow  = g_xconv + (size_t)b * SEQ_L * D_INNER + d;
    const float* dtrow = g_dt    + (size_t)b * SEQ_L * D_INNER + d;
    const float* bcrow = g_xbc   + (size_t)b * SEQ_L * XBC_LD;
    const float* zrow  = g_xz    + (size_t)b * SEQ_L * (2 * D_INNER) + D_INNER + d;
    float*       yrow  = g_y     + (size_t)b * SEQ_L * D_INNER + d;

    float h = 0.f;
    for (int t = 0; t < SEQ_L; t++) {
        float xv  = xrow [(size_t)t * D_INNER];
        float dtv = dtrow[(size_t)t * D_INNER];
        float Bv  = bcrow[t * XBC_LD + DT_RANK + s];
        float Cv  = bcrow[t * XBC_LD + DT_RANK + D_STATE + s];

        // h = h + dt*(A*h) + dt*(B*x)
        h = fmaf(dtv, fmaf(Acoef, h, Bv * xv), h);

        float p = h * Cv;
        p += __shfl_xor_sync(0xffffffffu, p, 8);
        p += __shfl_xor_sync(0xffffffffu, p, 4);
        p += __shfl_xor_sync(0xffffffffu, p, 2);
        p += __shfl_xor_sync(0xffffffffu, p, 1);

        if (s == 0) {
            float zv = zrow[(size_t)t * (2 * D_INNER)];
            float y  = fmaf(Dv, xv, p);
            y *= zv / (1.f + expf(-zv));       // * silu(z)
            yrow[(size_t)t * D_INNER] = y;
        }
    }
}

// ---------------- launch ----------------
extern "C" void kernel_launch(void* const* d_in, const int* in_sizes, int n_in,
                              void* d_out, int out_size)
{
    const float* x          = (const float*)d_in[0];
    const float* in_proj_w  = (const float*)d_in[1];
    const float* conv_w     = (const float*)d_in[2];
    const float* conv_b     = (const float*)d_in[3];
    const float* A_log      = (const float*)d_in[4];
    const float* Dp         = (const float*)d_in[5];
    const float* dt_proj_w  = (const float*)d_in[6];
    const float* dt_proj_b  = (const float*)d_in[7];
    const float* x_proj_w   = (const float*)d_in[8];
    const float* B_proj_w   = (const float*)d_in[9];
    const float* C_proj_w   = (const float*)d_in[10];
    const float* out_proj_w = (const float*)d_in[11];
    float* out = (float*)d_out;

    // resolve scratch addresses
    float *xz, *xconv, *xbc, *dt, *y, *wcat;
    cudaGetSymbolAddress((void**)&xz,    g_xz);
    cudaGetSymbolAddress((void**)&xconv, g_xconv);
    cudaGetSymbolAddress((void**)&xbc,   g_xbc);
    cudaGetSymbolAddress((void**)&dt,    g_dt);
    cudaGetSymbolAddress((void**)&y,     g_y);
    cudaGetSymbolAddress((void**)&wcat,  g_wcat);

    // pack [x_proj_w; B_proj_w; C_proj_w] -> g_wcat rows 0..95 (rows 96..127 stay zero)
    cudaMemcpyToSymbolAsync(g_wcat, x_proj_w, (size_t)DT_RANK * D_INNER * sizeof(float),
                            0, cudaMemcpyDeviceToDevice, 0);
    cudaMemcpyToSymbolAsync(g_wcat, B_proj_w, (size_t)D_STATE * D_INNER * sizeof(float),
                            (size_t)DT_RANK * D_INNER * sizeof(float), cudaMemcpyDeviceToDevice, 0);
    cudaMemcpyToSymbolAsync(g_wcat, C_proj_w, (size_t)D_STATE * D_INNER * sizeof(float),
                            (size_t)(DT_RANK + D_STATE) * D_INNER * sizeof(float), cudaMemcpyDeviceToDevice, 0);

    // 1) in_proj: xz = x @ in_proj_w^T   (M=4096, N=4096, K=1024)
    {
        dim3 grid(2 * D_INNER / 128, M_TOTAL / 128);
        tc_gemm<0><<<grid, 256>>>(x, D_MODEL, in_proj_w, D_MODEL, nullptr,
                                  xz, 2 * D_INNER, D_MODEL);
    }

    // 2) causal depthwise conv + silu -> g_xconv
    {
        int n = M_TOTAL * D_INNER;
        conv_silu_kernel<<<(n + 255) / 256, 256>>>(conv_w, conv_b);
    }

    // 3) fused x/B/C projection: xbc = xconv @ wcat^T  (M=4096, N=128(pad), K=2048)
    {
        dim3 grid(1, M_TOTAL / 128);
        tc_gemm<0><<<grid, 256>>>(xconv, D_INNER, wcat, D_INNER, nullptr,
                                  xbc, XBC_LD, D_INNER);
    }

    // 4) dt = softplus(xbc[:, :64] @ dt_proj_w^T + dt_proj_b)  (M=4096, N=2048, K=64)
    {
        dim3 grid(D_INNER / 128, M_TOTAL / 128);
        tc_gemm<1><<<grid, 256>>>(xbc, XBC_LD, dt_proj_w, DT_RANK, dt_proj_b,
                                  dt, D_INNER, DT_RANK);
    }

    // 5) selective scan + D skip + silu(z) gating -> g_y
    scan_kernel<<<256, 256>>>(A_log, Dp);

    // 6) out = y @ out_proj_w^T   (M=4096, N=1024, K=2048)
    {
        dim3 grid(D_MODEL / 128, M_TOTAL / 128);
        tc_gemm<0><<<grid, 256>>>(y, D_INNER, out_proj_w, D_INNER, nullptr,
                                  out, D_MODEL, D_INNER);
    }
}

// round 7
// speedup vs baseline: 1.6005x; 1.2563x over previous
#include <cuda_runtime.h>
#include <math.h>
#include <stdint.h>

// ---------------- problem constants ----------------
#define B_SZ    2
#define SEQ_L   2048
#define D_MODEL 1024
#define D_STATE 16
#define D_CONV  4
#define D_INNER 2048
#define DT_RANK 64
#define M_TOTAL (B_SZ * SEQ_L)   // 4096 tokens
#define XBC_LD  128              // padded row stride for xbc / wcat

// ---------------- scratch (device globals; no allocation allowed) ----------------
__device__ float g_xz[(size_t)M_TOTAL * 2 * D_INNER];   // in_proj output: [4096, 4096] (x_in | z)
__device__ float g_xconv[(size_t)M_TOTAL * D_INNER];    // conv+silu output
__device__ float g_xbc[(size_t)M_TOTAL * XBC_LD];       // [xdt(64) | B(16) | C(16) | pad(32)]
__device__ float g_dt[(size_t)M_TOTAL * D_INNER];       // softplus dt
__device__ float g_y[(size_t)M_TOTAL * D_INNER];        // scan output (gated)
__device__ float g_wcat[XBC_LD * D_INNER];              // [x_proj_w; B_proj_w; C_proj_w; zeros]

// ---------------- tf32 helpers ----------------
__device__ __forceinline__ uint32_t f2tf32(float f) {
    uint32_t r;
    asm("cvt.rna.tf32.f32 %0, %1;" : "=r"(r) : "f"(f));
    return r;
}

__device__ __forceinline__ void mma_tf32(float* c, const uint32_t* a, const uint32_t* b) {
    asm volatile(
        "mma.sync.aligned.m16n8k8.row.col.f32.tf32.tf32.f32 "
        "{%0,%1,%2,%3},{%4,%5,%6,%7},{%8,%9},{%0,%1,%2,%3};"
        : "+f"(c[0]), "+f"(c[1]), "+f"(c[2]), "+f"(c[3])
        : "r"(a[0]), "r"(a[1]), "r"(a[2]), "r"(a[3]), "r"(b[0]), "r"(b[1]));
}

// ================= tf32 mma.sync GEMM =================
// C[m,n] = act( sum_k A[m,k] * W[n,k] (+ bias[n]) )
// BM = BN = 128, BK = 16. 256 threads = 8 warps (2 along m, 4 along n).
// Warp tile 64x32 -> 4 m16-tiles x 4 n8-tiles = 16 mma per k8 step.
// smem tiles are m-major with pitch 20 words: loader does STS.128 (4 k-floats),
// consumer fragment LDS.32 pattern (g*20+tg) mod 32 covers all banks.
// Loader: 4 lanes per row (float4 each) -> 8 lines per warp LDG (coalesced).
// ACT: 0 = none, 1 = softplus(v + bias[n])
#define PITCH 20
template<int ACT>
__global__ __launch_bounds__(256)
void tc_gemm(const float* __restrict__ A, int lda,
             const float* __restrict__ W, int ldw,
             const float* __restrict__ bias,
             float* __restrict__ C, int ldc, int K)
{
    __shared__ uint32_t As[2][128 * PITCH];
    __shared__ uint32_t Bs[2][128 * PITCH];

    const int tid  = threadIdx.x;
    const int wid  = tid >> 5;
    const int lane = tid & 31;
    const int g    = lane >> 2;       // group id 0..7
    const int tg   = lane & 3;        // thread-in-group 0..3
    const int wm   = (wid & 1) * 64;  // warp m offset
    const int wn   = (wid >> 1) * 32; // warp n offset
    const int m0   = blockIdx.y * 128;
    const int n0   = blockIdx.x * 128;

    // loader mapping: thread t -> rows {t>>2, (t>>2)+64}, float4 slot (t&3)
    const int c4 = tid & 3;
    const int r0 = tid >> 2;          // 0..63
    const float* aP = A + (size_t)(m0 + r0) * lda + c4 * 4;
    const float* wP = W + (size_t)(n0 + r0) * ldw + c4 * 4;
    const size_t aStep = (size_t)64 * lda;
    const size_t wStep = (size_t)64 * ldw;
    const int sOff0 = r0 * PITCH + c4 * 4;
    const int sOff1 = (r0 + 64) * PITCH + c4 * 4;

    float acc[4][4][4];
#pragma unroll
    for (int i = 0; i < 4; i++)
#pragma unroll
        for (int j = 0; j < 4; j++)
#pragma unroll
            for (int q = 0; q < 4; q++) acc[i][j][q] = 0.f;

    const int KC = K / 16;
    float4 va0, va1, vb0, vb1;

    // preload chunk 0
    va0 = *(const float4*)(aP);          va1 = *(const float4*)(aP + aStep);
    vb0 = *(const float4*)(wP);          vb1 = *(const float4*)(wP + wStep);
    {
        *(uint4*)&As[0][sOff0] = make_uint4(f2tf32(va0.x), f2tf32(va0.y), f2tf32(va0.z), f2tf32(va0.w));
        *(uint4*)&As[0][sOff1] = make_uint4(f2tf32(va1.x), f2tf32(va1.y), f2tf32(va1.z), f2tf32(va1.w));
        *(uint4*)&Bs[0][sOff0] = make_uint4(f2tf32(vb0.x), f2tf32(vb0.y), f2tf32(vb0.z), f2tf32(vb0.w));
        *(uint4*)&Bs[0][sOff1] = make_uint4(f2tf32(vb1.x), f2tf32(vb1.y), f2tf32(vb1.z), f2tf32(vb1.w));
    }
    __syncthreads();

    for (int c = 0; c < KC; c++) {
        const int buf = c & 1;
        if (c + 1 < KC) {             // prefetch next chunk into regs
            const int k0 = (c + 1) * 16;
            va0 = *(const float4*)(aP + k0);  va1 = *(const float4*)(aP + aStep + k0);
            vb0 = *(const float4*)(wP + k0);  vb1 = *(const float4*)(wP + wStep + k0);
        }

        // per-warp fragment base pointers (precomputed, all indices constant)
        const uint32_t* sAw = As[buf] + (wm + g) * PITCH + tg;
        const uint32_t* sBw = Bs[buf] + (wn + g) * PITCH + tg;
#pragma unroll
        for (int ks = 0; ks < 2; ks++) {
            const int kb = ks * 8;
            uint32_t af[4][4], bf[4][2];
#pragma unroll
            for (int mt = 0; mt < 4; mt++) {
                af[mt][0] = sAw[mt * 16 * PITCH + kb];
                af[mt][1] = sAw[mt * 16 * PITCH + 8 * PITCH + kb];
                af[mt][2] = sAw[mt * 16 * PITCH + kb + 4];
                af[mt][3] = sAw[mt * 16 * PITCH + 8 * PITCH + kb + 4];
            }
#pragma unroll
            for (int nt = 0; nt < 4; nt++) {
                bf[nt][0] = sBw[nt * 8 * PITCH + kb];
                bf[nt][1] = sBw[nt * 8 * PITCH + kb + 4];
            }
#pragma unroll
            for (int mt = 0; mt < 4; mt++)
#pragma unroll
                for (int nt = 0; nt < 4; nt++)
                    mma_tf32(acc[mt][nt], af[mt], bf[nt]);
        }
        __syncthreads();

        if (c + 1 < KC) {             // stage prefetched regs into other buffer
            *(uint4*)&As[buf ^ 1][sOff0] = make_uint4(f2tf32(va0.x), f2tf32(va0.y), f2tf32(va0.z), f2tf32(va0.w));
            *(uint4*)&As[buf ^ 1][sOff1] = make_uint4(f2tf32(va1.x), f2tf32(va1.y), f2tf32(va1.z), f2tf32(va1.w));
            *(uint4*)&Bs[buf ^ 1][sOff0] = make_uint4(f2tf32(vb0.x), f2tf32(vb0.y), f2tf32(vb0.z), f2tf32(vb0.w));
            *(uint4*)&Bs[buf ^ 1][sOff1] = make_uint4(f2tf32(vb1.x), f2tf32(vb1.y), f2tf32(vb1.z), f2tf32(vb1.w));
            __syncthreads();
        }
    }

    // ---- epilogue: registers -> gmem (float2 per fragment row) ----
#pragma unroll
    for (int mt = 0; mt < 4; mt++) {
#pragma unroll
        for (int nt = 0; nt < 4; nt++) {
            const int row = m0 + wm + mt * 16 + g;
            const int col = n0 + wn + nt * 8 + 2 * tg;
            float v0 = acc[mt][nt][0], v1 = acc[mt][nt][1];
            float v2 = acc[mt][nt][2], v3 = acc[mt][nt][3];
            if (ACT == 1) {
                float b0 = bias[col], b1 = bias[col + 1];
                v0 += b0; v1 += b1; v2 += b0; v3 += b1;
                v0 = (v0 > 20.f) ? v0 : log1pf(expf(v0));
                v1 = (v1 > 20.f) ? v1 : log1pf(expf(v1));
                v2 = (v2 > 20.f) ? v2 : log1pf(expf(v2));
                v3 = (v3 > 20.f) ? v3 : log1pf(expf(v3));
            }
            *(float2*)(C + (size_t)row * ldc + col)       = make_float2(v0, v1);
            *(float2*)(C + (size_t)(row + 8) * ldc + col) = make_float2(v2, v3);
        }
    }
}

// ---------------- causal depthwise conv (width 4) + SiLU ----------------
__global__ void conv_silu_kernel(const float* __restrict__ conv_w,
                                 const float* __restrict__ conv_b)
{
    int idx = blockIdx.x * blockDim.x + threadIdx.x;
    if (idx >= M_TOTAL * D_INNER) return;
    int d  = idx % D_INNER;
    int ml = idx / D_INNER;      // b*L + l
    int l  = ml % SEQ_L;

    float acc = conv_b[d];
    const float* w = conv_w + d * D_CONV;
#pragma unroll
    for (int j = 0; j < D_CONV; j++) {
        int li = l - (D_CONV - 1) + j;
        if (li >= 0)
            acc = fmaf(w[j], g_xz[(size_t)(ml - (D_CONV - 1) + j) * (2 * D_INNER) + d], acc);
    }
    g_xconv[idx] = acc / (1.f + expf(-acc));   // silu
}

// ---------------- selective scan (+ D skip + z gating) ----------------
// 16 lanes = 16 states per channel; 2 channels per warp; 2048 warps total.
// Software-pipelined: t+1 loads issued before t's shfl chain.
__global__ void scan_kernel(const float* __restrict__ A_log,
                            const float* __restrict__ Dp)
{
    int gwarp = (blockIdx.x * blockDim.x + threadIdx.x) >> 5;
    int lane  = threadIdx.x & 31;
    int half  = lane >> 4;       // which channel within the warp
    int s     = lane & 15;       // state index
    int ch    = gwarp * 2 + half;        // 0..4095
    int b     = ch / D_INNER;
    int d     = ch % D_INNER;

    const float Acoef = -expf(A_log[d * D_STATE + s]);
    const float Dv    = Dp[d];

    const float* xrow  = g_xconv + (size_t)b * SEQ_L * D_INNER + d;
    const float* dtrow = g_dt    + (size_t)b * SEQ_L * D_INNER + d;
    const float* bcrow = g_xbc   + (size_t)b * SEQ_L * XBC_LD;
    const float* zrow  = g_xz    + (size_t)b * SEQ_L * (2 * D_INNER) + D_INNER + d;
    float*       yrow  = g_y     + (size_t)b * SEQ_L * D_INNER + d;

    float h  = 0.f;
    float xv  = xrow[0];
    float dtv = dtrow[0];
    float Bv  = bcrow[DT_RANK + s];
    float Cv  = bcrow[DT_RANK + D_STATE + s];

    for (int t = 0; t < SEQ_L; t++) {
        const int tn = (t + 1 < SEQ_L) ? t + 1 : t;
        float xv_n  = xrow [(size_t)tn * D_INNER];
        float dtv_n = dtrow[(size_t)tn * D_INNER];
        float Bv_n  = bcrow[tn * XBC_LD + DT_RANK + s];
        float Cv_n  = bcrow[tn * XBC_LD + DT_RANK + D_STATE + s];

        // h = h + dt*(A*h) + dt*(B*x)
        h = fmaf(dtv, fmaf(Acoef, h, Bv * xv), h);

        float p = h * Cv;
        p += __shfl_xor_sync(0xffffffffu, p, 8);
        p += __shfl_xor_sync(0xffffffffu, p, 4);
        p += __shfl_xor_sync(0xffffffffu, p, 2);
        p += __shfl_xor_sync(0xffffffffu, p, 1);

        if (s == 0) {
            float zv = zrow[(size_t)t * (2 * D_INNER)];
            float y  = fmaf(Dv, xv, p);
            y *= zv / (1.f + expf(-zv));       // * silu(z)
            yrow[(size_t)t * D_INNER] = y;
        }
        xv = xv_n; dtv = dtv_n; Bv = Bv_n; Cv = Cv_n;
    }
}

// ---------------- launch ----------------
extern "C" void kernel_launch(void* const* d_in, const int* in_sizes, int n_in,
                              void* d_out, int out_size)
{
    const float* x          = (const float*)d_in[0];
    const float* in_proj_w  = (const float*)d_in[1];
    const float* conv_w     = (const float*)d_in[2];
    const float* conv_b     = (const float*)d_in[3];
    const float* A_log      = (const float*)d_in[4];
    const float* Dp         = (const float*)d_in[5];
    const float* dt_proj_w  = (const float*)d_in[6];
    const float* dt_proj_b  = (const float*)d_in[7];
    const float* x_proj_w   = (const float*)d_in[8];
    const float* B_proj_w   = (const float*)d_in[9];
    const float* C_proj_w   = (const float*)d_in[10];
    const float* out_proj_w = (const float*)d_in[11];
    float* out = (float*)d_out;

    // resolve scratch addresses
    float *xz, *xconv, *xbc, *dt, *y, *wcat;
    cudaGetSymbolAddress((void**)&xz,    g_xz);
    cudaGetSymbolAddress((void**)&xconv, g_xconv);
    cudaGetSymbolAddress((void**)&xbc,   g_xbc);
    cudaGetSymbolAddress((void**)&dt,    g_dt);
    cudaGetSymbolAddress((void**)&y,     g_y);
    cudaGetSymbolAddress((void**)&wcat,  g_wcat);

    // pack [x_proj_w; B_proj_w; C_proj_w] -> g_wcat rows 0..95 (rows 96..127 stay zero)
    cudaMemcpyToSymbolAsync(g_wcat, x_proj_w, (size_t)DT_RANK * D_INNER * sizeof(float),
                            0, cudaMemcpyDeviceToDevice, 0);
    cudaMemcpyToSymbolAsync(g_wcat, B_proj_w, (size_t)D_STATE * D_INNER * sizeof(float),
                            (size_t)DT_RANK * D_INNER * sizeof(float), cudaMemcpyDeviceToDevice, 0);
    cudaMemcpyToSymbolAsync(g_wcat, C_proj_w, (size_t)D_STATE * D_INNER * sizeof(float),
                            (size_t)(DT_RANK + D_STATE) * D_INNER * sizeof(float), cudaMemcpyDeviceToDevice, 0);

    // 1) in_proj: xz = x @ in_proj_w^T   (M=4096, N=4096, K=1024)
    {
        dim3 grid(2 * D_INNER / 128, M_TOTAL / 128);
        tc_gemm<0><<<grid, 256>>>(x, D_MODEL, in_proj_w, D_MODEL, nullptr,
                                  xz, 2 * D_INNER, D_MODEL);
    }

    // 2) causal depthwise conv + silu -> g_xconv
    {
        int n = M_TOTAL * D_INNER;
        conv_silu_kernel<<<(n + 255) / 256, 256>>>(conv_w, conv_b);
    }

    // 3) fused x/B/C projection: xbc = xconv @ wcat^T  (M=4096, N=128(pad), K=2048)
    {
        dim3 grid(1, M_TOTAL / 128);
        tc_gemm<0><<<grid, 256>>>(xconv, D_INNER, wcat, D_INNER, nullptr,
                                  xbc, XBC_LD, D_INNER);
    }

    // 4) dt = softplus(xbc[:, :64] @ dt_proj_w^T + dt_proj_b)  (M=4096, N=2048, K=64)
    {
        dim3 grid(D_INNER / 128, M_TOTAL / 128);
        tc_gemm<1><<<grid, 256>>>(xbc, XBC_LD, dt_proj_w, DT_RANK, dt_proj_b,
                                  dt, D_INNER, DT_RANK);
    }

    // 5) selective scan + D skip + silu(z) gating -> g_y
    scan_kernel<<<256, 256>>>(A_log, Dp);

    // 6) out = y @ out_proj_w^T   (M=4096, N=1024, K=2048)
    {
        dim3 grid(D_MODEL / 128, M_TOTAL / 128);
        tc_gemm<0><<<grid, 256>>>(y, D_INNER, out_proj_w, D_INNER, nullptr,
                                  out, D_MODEL, D_INNER);
    }
}

// round 9
// speedup vs baseline: 1.6494x; 1.0306x over previous
#include <cuda_runtime.h>
#include <math.h>
#include <stdint.h>

// ---------------- problem constants ----------------
#define B_SZ    2
#define SEQ_L   2048
#define D_MODEL 1024
#define D_STATE 16
#define D_CONV  4
#define D_INNER 2048
#define DT_RANK 64
#define M_TOTAL (B_SZ * SEQ_L)   // 4096 tokens
#define XBC_LD  128              // padded row stride for xbc / wcat

// ---------------- scratch (device globals; no allocation allowed) ----------------
__device__ float g_xz[(size_t)M_TOTAL * 2 * D_INNER];   // in_proj output: [4096, 4096] (x_in | z)
__device__ float g_xconv[(size_t)M_TOTAL * D_INNER];    // conv+silu output
__device__ float g_xbc[(size_t)M_TOTAL * XBC_LD];       // [xdt(64) | B(16) | C(16) | pad(32)]
__device__ float g_dt[(size_t)M_TOTAL * D_INNER];       // softplus dt
__device__ float g_y[(size_t)M_TOTAL * D_INNER];        // scan output (gated)
__device__ float g_wcat[XBC_LD * D_INNER];              // [x_proj_w; B_proj_w; C_proj_w; zeros]

// ---------------- tf32 helpers ----------------
__device__ __forceinline__ uint32_t f2tf32(float f) {
    uint32_t r;
    asm("cvt.rna.tf32.f32 %0, %1;" : "=r"(r) : "f"(f));
    return r;
}

__device__ __forceinline__ void mma_tf32(float* c, const uint32_t* a, const uint32_t* b) {
    asm volatile(
        "mma.sync.aligned.m16n8k8.row.col.f32.tf32.tf32.f32 "
        "{%0,%1,%2,%3},{%4,%5,%6,%7},{%8,%9},{%0,%1,%2,%3};"
        : "+f"(c[0]), "+f"(c[1]), "+f"(c[2]), "+f"(c[3])
        : "r"(a[0]), "r"(a[1]), "r"(a[2]), "r"(a[3]), "r"(b[0]), "r"(b[1]));
}

__device__ __forceinline__ void cp16(uint32_t dst, const void* src) {
    asm volatile("cp.async.cg.shared.global [%0], [%1], 16;" :: "r"(dst), "l"(src));
}
__device__ __forceinline__ void cp_commit() {
    asm volatile("cp.async.commit_group;" ::: "memory");
}
template<int N>
__device__ __forceinline__ void cp_wait() {
    asm volatile("cp.async.wait_group %0;" :: "n"(N) : "memory");
}

// ================= tf32 mma.sync GEMM, cp.async multistage =================
// C[m,n] = act( sum_k A[m,k] * W[n,k] (+ bias[n]) )
// BM = BN = 128, BK = 16, STAGES = 4. 256 threads = 8 warps (2 m x 4 n).
// Warp tile 64x32 -> 4 m16-tiles x 4 n8-tiles = 16 mma per k8 step.
// smem m-major, pitch 20 words: cp.async writes 16B row-chunks; consumer
// fragment LDS.32 pattern (g*20+tg) mod 32 covers all 32 banks.
// tf32 conversion (cvt.rna) happens in the consumer, after LDS.
// ACT: 0 = none, 1 = softplus(v + bias[n])
#define PITCH  20
#define STAGES 4
#define STW    (128 * PITCH)                  // words per tile per stage
#define GEMM_SMEM (STAGES * 2 * STW * 4)      // 81920 bytes

template<int ACT>
__global__ __launch_bounds__(256)
void tc_gemm(const float* __restrict__ A, int lda,
             const float* __restrict__ W, int ldw,
             const float* __restrict__ bias,
             float* __restrict__ C, int ldc, int K)
{
    extern __shared__ uint32_t sm[];

    const int tid  = threadIdx.x;
    const int wid  = tid >> 5;
    const int lane = tid & 31;
    const int g    = lane >> 2;       // group id 0..7
    const int tg   = lane & 3;        // thread-in-group 0..3
    const int wm   = (wid & 1) * 64;  // warp m offset
    const int wn   = (wid >> 1) * 32; // warp n offset
    const int m0   = blockIdx.y * 128;
    const int n0   = blockIdx.x * 128;

    // loader mapping: thread t -> rows {t>>2, (t>>2)+64}, float4 slot (t&3)
    const int c4 = tid & 3;
    const int r0 = tid >> 2;          // 0..63
    const float* aP = A + (size_t)(m0 + r0) * lda + c4 * 4;
    const float* wP = W + (size_t)(n0 + r0) * ldw + c4 * 4;
    const size_t aStep = (size_t)64 * lda;
    const size_t wStep = (size_t)64 * ldw;

    uint32_t sbase;
    asm("{ .reg .u64 t; cvta.to.shared.u64 t, %1; cvt.u32.u64 %0, t; }" : "=r"(sbase) : "l"(sm));
    const uint32_t dOff0 = (uint32_t)(r0 * PITCH + c4 * 4) * 4;          // bytes
    const uint32_t dOff1 = (uint32_t)((r0 + 64) * PITCH + c4 * 4) * 4;

    const int KC = K / 16;

    // prologue: issue chunks 0..STAGES-2
#pragma unroll
    for (int s = 0; s < STAGES - 1; s++) {
        if (s < KC) {
            const uint32_t aB = sbase + (uint32_t)(s * STW) * 4;
            const uint32_t bB = sbase + (uint32_t)((STAGES + s) * STW) * 4;
            const int k0 = s * 16;
            cp16(aB + dOff0, aP + k0);  cp16(aB + dOff1, aP + aStep + k0);
            cp16(bB + dOff0, wP + k0);  cp16(bB + dOff1, wP + wStep + k0);
        }
        cp_commit();
    }

    float acc[4][4][4];
#pragma unroll
    for (int i = 0; i < 4; i++)
#pragma unroll
        for (int j = 0; j < 4; j++)
#pragma unroll
            for (int q = 0; q < 4; q++) acc[i][j][q] = 0.f;

    for (int c = 0; c < KC; c++) {
        cp_wait<STAGES - 2>();        // chunk c complete (for this thread)
        __syncthreads();              // ...for all threads; prior reads of reuse buf done

        // issue chunk c+STAGES-1 into buffer consumed at iteration c-1
        {
            const int cn = c + STAGES - 1;
            if (cn < KC) {
                const int buf = cn & (STAGES - 1);
                const uint32_t aB = sbase + (uint32_t)(buf * STW) * 4;
                const uint32_t bB = sbase + (uint32_t)((STAGES + buf) * STW) * 4;
                const int k0 = cn * 16;
                cp16(aB + dOff0, aP + k0);  cp16(aB + dOff1, aP + aStep + k0);
                cp16(bB + dOff0, wP + k0);  cp16(bB + dOff1, wP + wStep + k0);
            }
            cp_commit();
        }

        // consume chunk c
        const int buf = c & (STAGES - 1);
        const float* sA = (const float*)(sm + buf * STW);
        const float* sB = (const float*)(sm + (STAGES + buf) * STW);
        const float* sAw = sA + (wm + g) * PITCH + tg;
        const float* sBw = sB + (wn + g) * PITCH + tg;
#pragma unroll
        for (int ks = 0; ks < 2; ks++) {
            const int kb = ks * 8;
            uint32_t af[4][4], bf[4][2];
#pragma unroll
            for (int mt = 0; mt < 4; mt++) {
                af[mt][0] = f2tf32(sAw[mt * 16 * PITCH + kb]);
                af[mt][1] = f2tf32(sAw[mt * 16 * PITCH + 8 * PITCH + kb]);
                af[mt][2] = f2tf32(sAw[mt * 16 * PITCH + kb + 4]);
                af[mt][3] = f2tf32(sAw[mt * 16 * PITCH + 8 * PITCH + kb + 4]);
            }
#pragma unroll
            for (int nt = 0; nt < 4; nt++) {
                bf[nt][0] = f2tf32(sBw[nt * 8 * PITCH + kb]);
                bf[nt][1] = f2tf32(sBw[nt * 8 * PITCH + kb + 4]);
            }
#pragma unroll
            for (int mt = 0; mt < 4; mt++)
#pragma unroll
                for (int nt = 0; nt < 4; nt++)
                    mma_tf32(acc[mt][nt], af[mt], bf[nt]);
        }
    }

    // ---- epilogue: registers -> gmem (float2 per fragment row) ----
#pragma unroll
    for (int mt = 0; mt < 4; mt++) {
#pragma unroll
        for (int nt = 0; nt < 4; nt++) {
            const int row = m0 + wm + mt * 16 + g;
            const int col = n0 + wn + nt * 8 + 2 * tg;
            float v0 = acc[mt][nt][0], v1 = acc[mt][nt][1];
            float v2 = acc[mt][nt][2], v3 = acc[mt][nt][3];
            if (ACT == 1) {
                float b0 = bias[col], b1 = bias[col + 1];
                v0 += b0; v1 += b1; v2 += b0; v3 += b1;
                v0 = (v0 > 20.f) ? v0 : log1pf(expf(v0));
                v1 = (v1 > 20.f) ? v1 : log1pf(expf(v1));
                v2 = (v2 > 20.f) ? v2 : log1pf(expf(v2));
                v3 = (v3 > 20.f) ? v3 : log1pf(expf(v3));
            }
            *(float2*)(C + (size_t)row * ldc + col)       = make_float2(v0, v1);
            *(float2*)(C + (size_t)(row + 8) * ldc + col) = make_float2(v2, v3);
        }
    }
}

// ---------------- causal depthwise conv (width 4) + SiLU ----------------
__global__ void conv_silu_kernel(const float* __restrict__ conv_w,
                                 const float* __restrict__ conv_b)
{
    int idx = blockIdx.x * blockDim.x + threadIdx.x;
    if (idx >= M_TOTAL * D_INNER) return;
    int d  = idx % D_INNER;
    int ml = idx / D_INNER;      // b*L + l
    int l  = ml % SEQ_L;

    float acc = conv_b[d];
    const float* w = conv_w + d * D_CONV;
#pragma unroll
    for (int j = 0; j < D_CONV; j++) {
        int li = l - (D_CONV - 1) + j;
        if (li >= 0)
            acc = fmaf(w[j], g_xz[(size_t)(ml - (D_CONV - 1) + j) * (2 * D_INNER) + d], acc);
    }
    g_xconv[idx] = acc / (1.f + expf(-acc));   // silu
}

// ---------------- selective scan (+ D skip + z gating) ----------------
// 16 lanes = 16 states per channel; 2 channels per warp; 2048 warps total.
// Software-pipelined: t+1 loads issued before t's shfl chain.
__global__ void scan_kernel(const float* __restrict__ A_log,
                            const float* __restrict__ Dp)
{
    int gwarp = (blockIdx.x * blockDim.x + threadIdx.x) >> 5;
    int lane  = threadIdx.x & 31;
    int half  = lane >> 4;       // which channel within the warp
    int s     = lane & 15;       // state index
    int ch    = gwarp * 2 + half;        // 0..4095
    int b     = ch / D_INNER;
    int d     = ch % D_INNER;

    const float Acoef = -expf(A_log[d * D_STATE + s]);
    const float Dv    = Dp[d];

    const float* xrow  = g_xconv + (size_t)b * SEQ_L * D_INNER + d;
    const float* dtrow = g_dt    + (size_t)b * SEQ_L * D_INNER + d;
    const float* bcrow = g_xbc   + (size_t)b * SEQ_L * XBC_LD;
    const float* zrow  = g_xz    + (size_t)b * SEQ_L * (2 * D_INNER) + D_INNER + d;
    float*       yrow  = g_y     + (size_t)b * SEQ_L * D_INNER + d;

    float h  = 0.f;
    float xv  = xrow[0];
    float dtv = dtrow[0];
    float Bv  = bcrow[DT_RANK + s];
    float Cv  = bcrow[DT_RANK + D_STATE + s];

    for (int t = 0; t < SEQ_L; t++) {
        const int tn = (t + 1 < SEQ_L) ? t + 1 : t;
        float xv_n  = xrow [(size_t)tn * D_INNER];
        float dtv_n = dtrow[(size_t)tn * D_INNER];
        float Bv_n  = bcrow[tn * XBC_LD + DT_RANK + s];
        float Cv_n  = bcrow[tn * XBC_LD + DT_RANK + D_STATE + s];

        // h = h + dt*(A*h) + dt*(B*x)
        h = fmaf(dtv, fmaf(Acoef, h, Bv * xv), h);

        float p = h * Cv;
        p += __shfl_xor_sync(0xffffffffu, p, 8);
        p += __shfl_xor_sync(0xffffffffu, p, 4);
        p += __shfl_xor_sync(0xffffffffu, p, 2);
        p += __shfl_xor_sync(0xffffffffu, p, 1);

        if (s == 0) {
            float zv = zrow[(size_t)t * (2 * D_INNER)];
            float y  = fmaf(Dv, xv, p);
            y *= zv / (1.f + expf(-zv));       // * silu(z)
            yrow[(size_t)t * D_INNER] = y;
        }
        xv = xv_n; dtv = dtv_n; Bv = Bv_n; Cv = Cv_n;
    }
}

// ---------------- launch ----------------
extern "C" void kernel_launch(void* const* d_in, const int* in_sizes, int n_in,
                              void* d_out, int out_size)
{
    const float* x          = (const float*)d_in[0];
    const float* in_proj_w  = (const float*)d_in[1];
    const float* conv_w     = (const float*)d_in[2];
    const float* conv_b     = (const float*)d_in[3];
    const float* A_log      = (const float*)d_in[4];
    const float* Dp         = (const float*)d_in[5];
    const float* dt_proj_w  = (const float*)d_in[6];
    const float* dt_proj_b  = (const float*)d_in[7];
    const float* x_proj_w   = (const float*)d_in[8];
    const float* B_proj_w   = (const float*)d_in[9];
    const float* C_proj_w   = (const float*)d_in[10];
    const float* out_proj_w = (const float*)d_in[11];
    float* out = (float*)d_out;

    // resolve scratch addresses
    float *xz, *xconv, *xbc, *dt, *y, *wcat;
    cudaGetSymbolAddress((void**)&xz,    g_xz);
    cudaGetSymbolAddress((void**)&xconv, g_xconv);
    cudaGetSymbolAddress((void**)&xbc,   g_xbc);
    cudaGetSymbolAddress((void**)&dt,    g_dt);
    cudaGetSymbolAddress((void**)&y,     g_y);
    cudaGetSymbolAddress((void**)&wcat,  g_wcat);

    cudaFuncSetAttribute(tc_gemm<0>, cudaFuncAttributeMaxDynamicSharedMemorySize, GEMM_SMEM);
    cudaFuncSetAttribute(tc_gemm<1>, cudaFuncAttributeMaxDynamicSharedMemorySize, GEMM_SMEM);

    // pack [x_proj_w; B_proj_w; C_proj_w] -> g_wcat rows 0..95 (rows 96..127 stay zero)
    cudaMemcpyToSymbolAsync(g_wcat, x_proj_w, (size_t)DT_RANK * D_INNER * sizeof(float),
                            0, cudaMemcpyDeviceToDevice, 0);
    cudaMemcpyToSymbolAsync(g_wcat, B_proj_w, (size_t)D_STATE * D_INNER * sizeof(float),
                            (size_t)DT_RANK * D_INNER * sizeof(float), cudaMemcpyDeviceToDevice, 0);
    cudaMemcpyToSymbolAsync(g_wcat, C_proj_w, (size_t)D_STATE * D_INNER * sizeof(float),
                            (size_t)(DT_RANK + D_STATE) * D_INNER * sizeof(float), cudaMemcpyDeviceToDevice, 0);

    // 1) in_proj: xz = x @ in_proj_w^T   (M=4096, N=4096, K=1024)
    {
        dim3 grid(2 * D_INNER / 128, M_TOTAL / 128);
        tc_gemm<0><<<grid, 256, GEMM_SMEM>>>(x, D_MODEL, in_proj_w, D_MODEL, nullptr,
                                             xz, 2 * D_INNER, D_MODEL);
    }

    // 2) causal depthwise conv + silu -> g_xconv
    {
        int n = M_TOTAL * D_INNER;
        conv_silu_kernel<<<(n + 255) / 256, 256>>>(conv_w, conv_b);
    }

    // 3) fused x/B/C projection: xbc = xconv @ wcat^T  (M=4096, N=128(pad), K=2048)
    {
        dim3 grid(1, M_TOTAL / 128);
        tc_gemm<0><<<grid, 256, GEMM_SMEM>>>(xconv, D_INNER, wcat, D_INNER, nullptr,
                                             xbc, XBC_LD, D_INNER);
    }

    // 4) dt = softplus(xbc[:, :64] @ dt_proj_w^T + dt_proj_b)  (M=4096, N=2048, K=64)
    {
        dim3 grid(D_INNER / 128, M_TOTAL / 128);
        tc_gemm<1><<<grid, 256, GEMM_SMEM>>>(xbc, XBC_LD, dt_proj_w, DT_RANK, dt_proj_b,
                                             dt, D_INNER, DT_RANK);
    }

    // 5) selective scan + D skip + silu(z) gating -> g_y
    scan_kernel<<<256, 256>>>(A_log, Dp);

    // 6) out = y @ out_proj_w^T   (M=4096, N=1024, K=2048)
    {
        dim3 grid(D_MODEL / 128, M_TOTAL / 128);
        tc_gemm<0><<<grid, 256, GEMM_SMEM>>>(y, D_INNER, out_proj_w, D_INNER, nullptr,
                                             out, D_MODEL, D_INNER);
    }
}

// round 10
// speedup vs baseline: 3.0081x; 1.8237x over previous
#include <cuda_runtime.h>
#include <math.h>
#include <stdint.h>

// ---------------- problem constants ----------------
#define B_SZ    2
#define SEQ_L   2048
#define D_MODEL 1024
#define D_STATE 16
#define D_CONV  4
#define D_INNER 2048
#define DT_RANK 64
#define M_TOTAL (B_SZ * SEQ_L)   // 4096 tokens
#define XBC_LD  128              // padded row stride for xbc / wcat

// ---------------- scratch (device globals; no allocation allowed) ----------------
__device__ float g_xz[(size_t)M_TOTAL * 2 * D_INNER];   // in_proj output: [4096, 4096] (x_in | z)
__device__ float g_xconv[(size_t)M_TOTAL * D_INNER];    // conv+silu output
__device__ float g_xbc[(size_t)M_TOTAL * XBC_LD];       // [xdt(64) | B(16) | C(16) | pad(32)]
__device__ float g_dt[(size_t)M_TOTAL * D_INNER];       // softplus dt
__device__ float g_y[(size_t)M_TOTAL * D_INNER];        // scan output (gated)
__device__ float g_wcat[XBC_LD * D_INNER];              // [x_proj_w; B_proj_w; C_proj_w; zeros]

// ---------------- tf32 helpers ----------------
__device__ __forceinline__ uint32_t f2tf32(float f) {
    uint32_t r;
    asm("cvt.rna.tf32.f32 %0, %1;" : "=r"(r) : "f"(f));
    return r;
}

__device__ __forceinline__ void mma_tf32(float* c, const uint32_t* a, const uint32_t* b) {
    asm volatile(
        "mma.sync.aligned.m16n8k8.row.col.f32.tf32.tf32.f32 "
        "{%0,%1,%2,%3},{%4,%5,%6,%7},{%8,%9},{%0,%1,%2,%3};"
        : "+f"(c[0]), "+f"(c[1]), "+f"(c[2]), "+f"(c[3])
        : "r"(a[0]), "r"(a[1]), "r"(a[2]), "r"(a[3]), "r"(b[0]), "r"(b[1]));
}

__device__ __forceinline__ void cp16(uint32_t dst, const void* src) {
    asm volatile("cp.async.cg.shared.global [%0], [%1], 16;" :: "r"(dst), "l"(src));
}
__device__ __forceinline__ void cp_commit() {
    asm volatile("cp.async.commit_group;" ::: "memory");
}
template<int N>
__device__ __forceinline__ void cp_wait() {
    asm volatile("cp.async.wait_group %0;" :: "n"(N) : "memory");
}

// ================= tf32 mma.sync GEMM, cp.async multistage =================
// C[m,n] = act( sum_k A[m,k] * W[n,k] (+ bias[n]) )
// BM = 128, BN = 64, BK = 16, STAGES = 4. 256 threads = 8 warps (2 m x 4 n).
// Warp tile 64x16 -> 4 m16-tiles x 2 n8-tiles = 8 mma per k8 step.
// 3 blocks/SM (launch_bounds): smem 60KB + ~84 regs.
// smem m-major, pitch 20 words; fragment LDS.32 pattern (g*20+tg) mod 32
// covers all banks. tf32 conversion (cvt.rna) in the consumer.
// ACT: 0 = none, 1 = softplus(v + bias[n])
#define PITCH  20
#define STAGES 4
#define STW_A  (128 * PITCH)
#define STW_B  (64 * PITCH)
#define GEMM_SMEM (STAGES * (STW_A + STW_B) * 4)   // 61440 bytes

template<int ACT>
__global__ __launch_bounds__(256, 3)
void tc_gemm(const float* __restrict__ A, int lda,
             const float* __restrict__ W, int ldw,
             const float* __restrict__ bias,
             float* __restrict__ C, int ldc, int K)
{
    extern __shared__ uint32_t sm[];

    const int tid  = threadIdx.x;
    const int wid  = tid >> 5;
    const int lane = tid & 31;
    const int g    = lane >> 2;       // group id 0..7
    const int tg   = lane & 3;        // thread-in-group 0..3
    const int wm   = (wid & 1) * 64;  // warp m offset
    const int wn   = (wid >> 1) * 16; // warp n offset
    const int m0   = blockIdx.y * 128;
    const int n0   = blockIdx.x * 64;

    // loader: A rows {t>>2, (t>>2)+64} (2 cp16), B row t>>2 (1 cp16); quad t&3
    const int c4 = tid & 3;
    const int r0 = tid >> 2;          // 0..63
    const float* aP = A + (size_t)(m0 + r0) * lda + c4 * 4;
    const float* wP = W + (size_t)(n0 + r0) * ldw + c4 * 4;
    const size_t aStep = (size_t)64 * lda;

    uint32_t sbase;
    asm("{ .reg .u64 t; cvta.to.shared.u64 t, %1; cvt.u32.u64 %0, t; }" : "=r"(sbase) : "l"(sm));
    const uint32_t dOffA0 = (uint32_t)(r0 * PITCH + c4 * 4) * 4;          // bytes
    const uint32_t dOffA1 = (uint32_t)((r0 + 64) * PITCH + c4 * 4) * 4;
    const uint32_t dOffB  = dOffA0;

    const int KC = K / 16;

    // prologue: issue chunks 0..STAGES-2
#pragma unroll
    for (int s = 0; s < STAGES - 1; s++) {
        if (s < KC) {
            const uint32_t aB = sbase + (uint32_t)(s * STW_A) * 4;
            const uint32_t bB = sbase + (uint32_t)(STAGES * STW_A + s * STW_B) * 4;
            const int k0 = s * 16;
            cp16(aB + dOffA0, aP + k0);  cp16(aB + dOffA1, aP + aStep + k0);
            cp16(bB + dOffB, wP + k0);
        }
        cp_commit();
    }

    float acc[4][2][4];
#pragma unroll
    for (int i = 0; i < 4; i++)
#pragma unroll
        for (int j = 0; j < 2; j++)
#pragma unroll
            for (int q = 0; q < 4; q++) acc[i][j][q] = 0.f;

    for (int c = 0; c < KC; c++) {
        cp_wait<STAGES - 2>();
        __syncthreads();

        // issue chunk c+STAGES-1 into the buffer consumed at iteration c-1
        {
            const int cn = c + STAGES - 1;
            if (cn < KC) {
                const int buf = cn & (STAGES - 1);
                const uint32_t aB = sbase + (uint32_t)(buf * STW_A) * 4;
                const uint32_t bB = sbase + (uint32_t)(STAGES * STW_A + buf * STW_B) * 4;
                const int k0 = cn * 16;
                cp16(aB + dOffA0, aP + k0);  cp16(aB + dOffA1, aP + aStep + k0);
                cp16(bB + dOffB, wP + k0);
            }
            cp_commit();
        }

        // consume chunk c
        const int buf = c & (STAGES - 1);
        const float* sAw = (const float*)(sm + buf * STW_A) + (wm + g) * PITCH + tg;
        const float* sBw = (const float*)(sm + STAGES * STW_A + buf * STW_B) + (wn + g) * PITCH + tg;
#pragma unroll
        for (int ks = 0; ks < 2; ks++) {
            const int kb = ks * 8;
            uint32_t af[4][4], bf[2][2];
#pragma unroll
            for (int mt = 0; mt < 4; mt++) {
                af[mt][0] = f2tf32(sAw[mt * 16 * PITCH + kb]);
                af[mt][1] = f2tf32(sAw[mt * 16 * PITCH + 8 * PITCH + kb]);
                af[mt][2] = f2tf32(sAw[mt * 16 * PITCH + kb + 4]);
                af[mt][3] = f2tf32(sAw[mt * 16 * PITCH + 8 * PITCH + kb + 4]);
            }
#pragma unroll
            for (int nt = 0; nt < 2; nt++) {
                bf[nt][0] = f2tf32(sBw[nt * 8 * PITCH + kb]);
                bf[nt][1] = f2tf32(sBw[nt * 8 * PITCH + kb + 4]);
            }
#pragma unroll
            for (int mt = 0; mt < 4; mt++)
#pragma unroll
                for (int nt = 0; nt < 2; nt++)
                    mma_tf32(acc[mt][nt], af[mt], bf[nt]);
        }
    }

    // ---- epilogue: registers -> gmem (float2 per fragment row) ----
#pragma unroll
    for (int mt = 0; mt < 4; mt++) {
#pragma unroll
        for (int nt = 0; nt < 2; nt++) {
            const int row = m0 + wm + mt * 16 + g;
            const int col = n0 + wn + nt * 8 + 2 * tg;
            float v0 = acc[mt][nt][0], v1 = acc[mt][nt][1];
            float v2 = acc[mt][nt][2], v3 = acc[mt][nt][3];
            if (ACT == 1) {
                float b0 = bias[col], b1 = bias[col + 1];
                v0 += b0; v1 += b1; v2 += b0; v3 += b1;
                v0 = (v0 > 20.f) ? v0 : __logf(1.f + __expf(v0));   // fast softplus
                v1 = (v1 > 20.f) ? v1 : __logf(1.f + __expf(v1));
                v2 = (v2 > 20.f) ? v2 : __logf(1.f + __expf(v2));
                v3 = (v3 > 20.f) ? v3 : __logf(1.f + __expf(v3));
            }
            *(float2*)(C + (size_t)row * ldc + col)       = make_float2(v0, v1);
            *(float2*)(C + (size_t)(row + 8) * ldc + col) = make_float2(v2, v3);
        }
    }
}

// ---------------- causal depthwise conv (width 4) + SiLU ----------------
__global__ void conv_silu_kernel(const float* __restrict__ conv_w,
                                 const float* __restrict__ conv_b)
{
    int idx = blockIdx.x * blockDim.x + threadIdx.x;
    if (idx >= M_TOTAL * D_INNER) return;
    int d  = idx % D_INNER;
    int ml = idx / D_INNER;      // b*L + l
    int l  = ml % SEQ_L;

    float acc = conv_b[d];
    const float* w = conv_w + d * D_CONV;
#pragma unroll
    for (int j = 0; j < D_CONV; j++) {
        int li = l - (D_CONV - 1) + j;
        if (li >= 0)
            acc = fmaf(w[j], g_xz[(size_t)(ml - (D_CONV - 1) + j) * (2 * D_INNER) + d], acc);
    }
    g_xconv[idx] = acc / (1.f + __expf(-acc));   // silu
}

// ---------------- selective scan (+ D skip + z gating) ----------------
// 8 channels per warp, 4 lanes per channel, 4 states per lane. 512 warps.
// float4 loads for A/B/C; 2-deep software pipeline; 2-shfl reduction.
__global__ void scan_kernel(const float* __restrict__ A_log,
                            const float* __restrict__ Dp)
{
    const int gwarp = (blockIdx.x * blockDim.x + threadIdx.x) >> 5;  // 0..511
    const int lane  = threadIdx.x & 31;
    const int cw    = lane >> 2;          // channel within warp 0..7
    const int q     = lane & 3;           // state quad 0..3 (states q*4..q*4+3)
    const int ch    = gwarp * 8 + cw;     // 0..4095
    const int b     = ch / D_INNER;
    const int d     = ch % D_INNER;

    const float4 Alog4 = *(const float4*)(A_log + d * D_STATE + q * 4);
    const float A0 = -__expf(Alog4.x), A1 = -__expf(Alog4.y);
    const float A2 = -__expf(Alog4.z), A3 = -__expf(Alog4.w);
    const float Dv = Dp[d];

    const float* xrow  = g_xconv + (size_t)b * SEQ_L * D_INNER + d;
    const float* dtrow = g_dt    + (size_t)b * SEQ_L * D_INNER + d;
    const float* bcrow = g_xbc   + (size_t)b * SEQ_L * XBC_LD;
    const float* zrow  = g_xz    + (size_t)b * SEQ_L * (2 * D_INNER) + D_INNER + d;
    float*       yrow  = g_y     + (size_t)b * SEQ_L * D_INNER + d;

    float h0 = 0.f, h1 = 0.f, h2 = 0.f, h3 = 0.f;

    // pipeline slots for t and t+1
    float  xvA  = xrow[0],                    xvB  = xrow[D_INNER];
    float  dtA  = dtrow[0],                   dtB  = dtrow[D_INNER];
    float4 Bf4A = *(const float4*)(bcrow + DT_RANK + q * 4);
    float4 Cf4A = *(const float4*)(bcrow + DT_RANK + D_STATE + q * 4);
    float4 Bf4B = *(const float4*)(bcrow + XBC_LD + DT_RANK + q * 4);
    float4 Cf4B = *(const float4*)(bcrow + XBC_LD + DT_RANK + D_STATE + q * 4);
    float  zvA = 0.f, zvB = 0.f;
    if (q == 0) { zvA = zrow[0]; zvB = zrow[2 * D_INNER]; }

#pragma unroll 1
    for (int t = 0; t < SEQ_L; t += 2) {
        // prefetch t+2 / t+3 (clamped)
        const int t2 = (t + 2 < SEQ_L) ? t + 2 : SEQ_L - 1;
        const int t3 = (t + 3 < SEQ_L) ? t + 3 : SEQ_L - 1;
        float  xv2  = xrow [(size_t)t2 * D_INNER];
        float  dt2  = dtrow[(size_t)t2 * D_INNER];
        float4 Bf42 = *(const float4*)(bcrow + t2 * XBC_LD + DT_RANK + q * 4);
        float4 Cf42 = *(const float4*)(bcrow + t2 * XBC_LD + DT_RANK + D_STATE + q * 4);
        float  xv3  = xrow [(size_t)t3 * D_INNER];
        float  dt3  = dtrow[(size_t)t3 * D_INNER];
        float4 Bf43 = *(const float4*)(bcrow + t3 * XBC_LD + DT_RANK + q * 4);
        float4 Cf43 = *(const float4*)(bcrow + t3 * XBC_LD + DT_RANK + D_STATE + q * 4);
        float  zv2 = 0.f, zv3 = 0.f;
        if (q == 0) { zv2 = zrow[(size_t)t2 * 2 * D_INNER]; zv3 = zrow[(size_t)t3 * 2 * D_INNER]; }

        // ---- step t ----
        h0 = fmaf(dtA, fmaf(A0, h0, Bf4A.x * xvA), h0);
        h1 = fmaf(dtA, fmaf(A1, h1, Bf4A.y * xvA), h1);
        h2 = fmaf(dtA, fmaf(A2, h2, Bf4A.z * xvA), h2);
        h3 = fmaf(dtA, fmaf(A3, h3, Bf4A.w * xvA), h3);
        {
            float p = fmaf(h3, Cf4A.w, fmaf(h2, Cf4A.z, fmaf(h1, Cf4A.y, h0 * Cf4A.x)));
            p += __shfl_xor_sync(0xffffffffu, p, 1);
            p += __shfl_xor_sync(0xffffffffu, p, 2);
            if (q == 0) {
                float y = fmaf(Dv, xvA, p);
                y *= zvA / (1.f + __expf(-zvA));
                yrow[(size_t)t * D_INNER] = y;
            }
        }

        // ---- step t+1 ----
        h0 = fmaf(dtB, fmaf(A0, h0, Bf4B.x * xvB), h0);
        h1 = fmaf(dtB, fmaf(A1, h1, Bf4B.y * xvB), h1);
        h2 = fmaf(dtB, fmaf(A2, h2, Bf4B.z * xvB), h2);
        h3 = fmaf(dtB, fmaf(A3, h3, Bf4B.w * xvB), h3);
        {
            float p = fmaf(h3, Cf4B.w, fmaf(h2, Cf4B.z, fmaf(h1, Cf4B.y, h0 * Cf4B.x)));
            p += __shfl_xor_sync(0xffffffffu, p, 1);
            p += __shfl_xor_sync(0xffffffffu, p, 2);
            if (q == 0) {
                float y = fmaf(Dv, xvB, p);
                y *= zvB / (1.f + __expf(-zvB));
                yrow[(size_t)(t + 1) * D_INNER] = y;
            }
        }

        xvA = xv2; dtA = dt2; Bf4A = Bf42; Cf4A = Cf42; zvA = zv2;
        xvB = xv3; dtB = dt3; Bf4B = Bf43; Cf4B = Cf43; zvB = zv3;
    }
}

// ---------------- launch ----------------
extern "C" void kernel_launch(void* const* d_in, const int* in_sizes, int n_in,
                              void* d_out, int out_size)
{
    const float* x          = (const float*)d_in[0];
    const float* in_proj_w  = (const float*)d_in[1];
    const float* conv_w     = (const float*)d_in[2];
    const float* conv_b     = (const float*)d_in[3];
    const float* A_log      = (const float*)d_in[4];
    const float* Dp         = (const float*)d_in[5];
    const float* dt_proj_w  = (const float*)d_in[6];
    const float* dt_proj_b  = (const float*)d_in[7];
    const float* x_proj_w   = (const float*)d_in[8];
    const float* B_proj_w   = (const float*)d_in[9];
    const float* C_proj_w   = (const float*)d_in[10];
    const float* out_proj_w = (const float*)d_in[11];
    float* out = (float*)d_out;

    // resolve scratch addresses
    float *xz, *xconv, *xbc, *dt, *y, *wcat;
    cudaGetSymbolAddress((void**)&xz,    g_xz);
    cudaGetSymbolAddress((void**)&xconv, g_xconv);
    cudaGetSymbolAddress((void**)&xbc,   g_xbc);
    cudaGetSymbolAddress((void**)&dt,    g_dt);
    cudaGetSymbolAddress((void**)&y,     g_y);
    cudaGetSymbolAddress((void**)&wcat,  g_wcat);

    cudaFuncSetAttribute(tc_gemm<0>, cudaFuncAttributeMaxDynamicSharedMemorySize, GEMM_SMEM);
    cudaFuncSetAttribute(tc_gemm<1>, cudaFuncAttributeMaxDynamicSharedMemorySize, GEMM_SMEM);

    // pack [x_proj_w; B_proj_w; C_proj_w] -> g_wcat rows 0..95 (rows 96..127 stay zero)
    cudaMemcpyToSymbolAsync(g_wcat, x_proj_w, (size_t)DT_RANK * D_INNER * sizeof(float),
                            0, cudaMemcpyDeviceToDevice, 0);
    cudaMemcpyToSymbolAsync(g_wcat, B_proj_w, (size_t)D_STATE * D_INNER * sizeof(float),
                            (size_t)DT_RANK * D_INNER * sizeof(float), cudaMemcpyDeviceToDevice, 0);
    cudaMemcpyToSymbolAsync(g_wcat, C_proj_w, (size_t)D_STATE * D_INNER * sizeof(float),
                            (size_t)(DT_RANK + D_STATE) * D_INNER * sizeof(float), cudaMemcpyDeviceToDevice, 0);

    // 1) in_proj: xz = x @ in_proj_w^T   (M=4096, N=4096, K=1024)
    {
        dim3 grid(2 * D_INNER / 64, M_TOTAL / 128);
        tc_gemm<0><<<grid, 256, GEMM_SMEM>>>(x, D_MODEL, in_proj_w, D_MODEL, nullptr,
                                             xz, 2 * D_INNER, D_MODEL);
    }

    // 2) causal depthwise conv + silu -> g_xconv
    {
        int n = M_TOTAL * D_INNER;
        conv_silu_kernel<<<(n + 255) / 256, 256>>>(conv_w, conv_b);
    }

    // 3) fused x/B/C projection: xbc = xconv @ wcat^T  (M=4096, N=128(pad), K=2048)
    {
        dim3 grid(XBC_LD / 64, M_TOTAL / 128);
        tc_gemm<0><<<grid, 256, GEMM_SMEM>>>(xconv, D_INNER, wcat, D_INNER, nullptr,
                                             xbc, XBC_LD, D_INNER);
    }

    // 4) dt = softplus(xbc[:, :64] @ dt_proj_w^T + dt_proj_b)  (M=4096, N=2048, K=64)
    {
        dim3 grid(D_INNER / 64, M_TOTAL / 128);
        tc_gemm<1><<<grid, 256, GEMM_SMEM>>>(xbc, XBC_LD, dt_proj_w, DT_RANK, dt_proj_b,
                                             dt, D_INNER, DT_RANK);
    }

    // 5) selective scan + D skip + silu(z) gating -> g_y
    scan_kernel<<<64, 256>>>(A_log, Dp);

    // 6) out = y @ out_proj_w^T   (M=4096, N=1024, K=2048)
    {
        dim3 grid(D_MODEL / 64, M_TOTAL / 128);
        tc_gemm<0><<<grid, 256, GEMM_SMEM>>>(y, D_INNER, out_proj_w, D_INNER, nullptr,
                                             out, D_MODEL, D_INNER);
    }
}